// round 11
// baseline (speedup 1.0000x reference)
#include <cuda_runtime.h>
#include <cuda_fp16.h>
#include <cstdint>

// ---------------------------------------------------------------------------
// Problem dims
// ---------------------------------------------------------------------------
#define N_DIM  8192
#define IN_CH  128
#define OUT_CH 64

// Big-GEMM tiling (mma.sync fp16; tcgen05 unavailable at compute_103)
#define TM       128               // M rows per tile
#define KB       32                // K per stage (fp16 elements)
#define SPLITK   16
#define KSPAN    (N_DIM / SPLITK)  // 512
#define NITER    (KSPAN / KB)      // 16
#define GTHREADS 256               // 8 warps in a 4x2 (M x N) grid of 32x32 tiles
#define NTILES   ((N_DIM / TM) * SPLITK)   // 1024
#define PERSIST  456               // 152 SMs x 3 CTAs

// Double-buffered SMEM: 64B rows, chunk swizzle c ^= (r>>1)&3 (16B chunks).
// Stage: A 8192 | B 4096 = 12288 B; x2 = 24576 B.
#define ST_A     0
#define ST_B     8192
#define STAGE    12288
#define S_TOTAL  24576

// ---------------------------------------------------------------------------
// Scratch (__device__ globals). Referenced ONLY from device code — never
// passed as kernel args from host (that was the R4/R5 bug).
// ---------------------------------------------------------------------------
__device__ __align__(16) float g_part[SPLITK * N_DIM * OUT_CH];  // 32 MB partials
__device__ __align__(16) __half g_bf[OUT_CH * N_DIM];            // B^T fp16, K-major
__device__ int g_ctr[2];                                         // tile queues

// ---------------------------------------------------------------------------
// PTX helpers (baseline ISA: ldmatrix + mma.sync only)
// ---------------------------------------------------------------------------
__device__ __forceinline__ uint32_t smem_u32(const void* p) {
    uint32_t a;
    asm("{ .reg .u64 t; cvta.to.shared.u64 t, %1; cvt.u32.u64 %0, t; }"
        : "=r"(a) : "l"(p));
    return a;
}
__device__ __forceinline__ void ldsm4(uint32_t* r, uint32_t addr) {
    asm volatile("ldmatrix.sync.aligned.m8n8.x4.shared.b16 {%0,%1,%2,%3}, [%4];"
                 : "=r"(r[0]), "=r"(r[1]), "=r"(r[2]), "=r"(r[3]) : "r"(addr));
}
__device__ __forceinline__ void mma16816(float* c, const uint32_t* a,
                                         uint32_t b0, uint32_t b1) {
    asm volatile(
        "mma.sync.aligned.m16n8k16.row.col.f32.f16.f16.f32 "
        "{%0,%1,%2,%3}, {%4,%5,%6,%7}, {%8,%9}, {%0,%1,%2,%3};"
        : "+f"(c[0]), "+f"(c[1]), "+f"(c[2]), "+f"(c[3])
        : "r"(a[0]), "r"(a[1]), "r"(a[2]), "r"(a[3]), "r"(b0), "r"(b1));
}

// ---------------------------------------------------------------------------
// Kernel 1: g_bf[n][k] = fp16( (features @ W)[k][n] ) + reset tile queues.
// ---------------------------------------------------------------------------
__global__ __launch_bounds__(256) void lin_kernel(
    const float* __restrict__ F, const float* __restrict__ W)
{
    if (blockIdx.x == 0 && threadIdx.x < 2) g_ctr[threadIdx.x] = 0;

    __shared__ float Ws[IN_CH][OUT_CH];
    const int tid = threadIdx.x;
    #pragma unroll
    for (int t = 0; t < 8; t++) {
        int idx = tid + t * 256;
        int r = idx >> 4, c4 = idx & 15;
        *reinterpret_cast<float4*>(&Ws[r][c4 * 4]) =
            *reinterpret_cast<const float4*>(&W[r * OUT_CH + c4 * 4]);
    }
    __syncthreads();

    const int row = blockIdx.x * 32 + (tid >> 3);   // k index (0..8191)
    const int c0  = (tid & 7) * 8;                  // n base
    float acc[8];
    #pragma unroll
    for (int j = 0; j < 8; j++) acc[j] = 0.0f;

    #pragma unroll 8
    for (int k = 0; k < IN_CH; k += 4) {
        float4 a4 = *reinterpret_cast<const float4*>(&F[row * IN_CH + k]);
        float av[4] = {a4.x, a4.y, a4.z, a4.w};
        #pragma unroll
        for (int kk = 0; kk < 4; kk++)
            #pragma unroll
            for (int j = 0; j < 8; j++)
                acc[j] = fmaf(av[kk], Ws[k + kk][c0 + j], acc[j]);
    }
    #pragma unroll
    for (int j = 0; j < 8; j++)
        g_bf[(size_t)(c0 + j) * N_DIM + row] = __float2half(acc[j]);
}

// ---------------------------------------------------------------------------
// Kernel 2: fp16 GEMM (mma.sync.m16n8k16), KB=32, double-buffered,
//           PERSISTENT CTAs pulling tiles from g_ctr[phase].
//   partial[s] = A[mTile, kspan_s] @ B^T      (B from g_bf)
// ---------------------------------------------------------------------------

// A: per thread 4 float4 (row aR, 16 floats at col aH*16); B: 1 uint4
#define LDG_TILE(it_) do {                                                      \
    _Pragma("unroll")                                                           \
    for (int j_ = 0; j_ < 4; j_++)                                              \
        stA[j_] = *reinterpret_cast<const float4*>(                             \
            Ablk + (size_t)aR * N_DIM + (it_) * KB + aH * 16 + j_ * 4);         \
    stB = *reinterpret_cast<const uint4*>(                                      \
        g_bf + (size_t)bRow * N_DIM + kBase + (it_) * KB + bC * 8);             \
} while (0)

// Convert fp32 -> fp16, store into stage buf_ (chunk-swizzled 64B rows)
#define STS_TILE(buf_) do {                                                     \
    char* sb_ = sm + (buf_) * STAGE;                                            \
    _Pragma("unroll")                                                           \
    for (int i_ = 0; i_ < 2; i_++) {       /* 16B chunk from 8 floats */        \
        float4 va_ = stA[i_ * 2], vb_ = stA[i_ * 2 + 1];                        \
        uint4 h_;                                                               \
        asm("cvt.rn.f16x2.f32 %0, %1, %2;" : "=r"(h_.x) : "f"(va_.y), "f"(va_.x)); \
        asm("cvt.rn.f16x2.f32 %0, %1, %2;" : "=r"(h_.y) : "f"(va_.w), "f"(va_.z)); \
        asm("cvt.rn.f16x2.f32 %0, %1, %2;" : "=r"(h_.z) : "f"(vb_.y), "f"(vb_.x)); \
        asm("cvt.rn.f16x2.f32 %0, %1, %2;" : "=r"(h_.w) : "f"(vb_.w), "f"(vb_.z)); \
        uint32_t c_   = (uint32_t)(aH * 2 + i_);                                \
        uint32_t off_ = (uint32_t)aR * 64 + ((c_ ^ aXor) << 4);                 \
        *reinterpret_cast<uint4*>(sb_ + ST_A + off_) = h_;                      \
    }                                                                           \
    {                                                                           \
        uint32_t off_ = (uint32_t)bRow * 64 + (((uint32_t)bC ^ bXorS) << 4);    \
        *reinterpret_cast<uint4*>(sb_ + ST_B + off_) = stB;                     \
    }                                                                           \
} while (0)

__global__ __launch_bounds__(GTHREADS, 3) void mma_gemm(
    const float* __restrict__ A, int phase)
{
    __shared__ __align__(128) char sm[S_TOTAL];
    __shared__ int s_tile;
    const uint32_t sbase = smem_u32(sm);

    const int tid = threadIdx.x;
    const int wid = tid >> 5;
    const int lid = tid & 31;
    const int wRow = wid >> 1;                // 0..3 -> rows wRow*32..+31
    const int wCol = wid & 1;                 // 0..1 -> cols wCol*32..+31

    // staging coords (tile-independent)
    const int aR = tid >> 1;
    const int aH = tid & 1;
    const uint32_t aXor = (uint32_t)((aR >> 1) & 3);
    const int bRow = tid >> 2;
    const int bC   = tid & 3;
    const uint32_t bXorS = (uint32_t)((bRow >> 1) & 3);

    // per-lane ldmatrix invariants
    const uint32_t rAL   = (uint32_t)(lid & 15);          // row-in-16 for A
    const uint32_t aFXor = (rAL >> 1) & 3u;
    const uint32_t aSel  = (uint32_t)(lid >> 4);
    const uint32_t rBL   = (uint32_t)((lid & 7) + ((lid >> 4) & 1) * 8);
    const uint32_t bFXor = (rBL >> 1) & 3u;
    const uint32_t bSel  = (uint32_t)((lid >> 3) & 1);

    float4 stA[4];
    uint4  stB;

    for (;;) {
        // ---- steal next tile ----
        if (tid == 0) s_tile = atomicAdd(&g_ctr[phase], 1);
        __syncthreads();
        const int t = s_tile;
        if (t >= NTILES) break;

        const int mBase = (t & 63) * TM;
        const int kBase = (t >> 6) * KSPAN;
        const float* Ablk = A + (size_t)mBase * N_DIM + kBase;

        float acc[8][4];
        #pragma unroll
        for (int q = 0; q < 8; q++)
            #pragma unroll
            for (int j = 0; j < 4; j++) acc[q][j] = 0.0f;

        // ---- prologue: fill stage 0 ----
        LDG_TILE(0);
        STS_TILE(0);
        __syncthreads();

        for (int it = 0; it < NITER; it++) {
            const uint32_t so = sbase + (uint32_t)(it & 1) * STAGE;

            if (it + 1 < NITER) LDG_TILE(it + 1);   // LDGs fly under compute

            #pragma unroll
            for (int ks = 0; ks < 2; ks++) {
                // A fragments: 2 row groups of 16 (warp rows wRow*32 + mg*16)
                uint32_t a0[4], a1[4];
                {
                    uint32_t aOff = (((uint32_t)(ks * 2) + aSel) ^ aFXor) << 4;
                    uint32_t base = so + ST_A +
                        ((uint32_t)(wRow * 32) + rAL) * 64 + aOff;
                    ldsm4(a0, base);
                    ldsm4(a1, base + 16 * 64);
                }
                // B fragments: 2 col groups of 16 (warp cols wCol*32 + bg*16)
                uint32_t bOff = (((uint32_t)(ks * 2) + bSel) ^ bFXor) << 4;
                #pragma unroll
                for (int bg = 0; bg < 2; bg++) {
                    uint32_t rB = (uint32_t)(wCol * 32 + bg * 16) + rBL;
                    uint32_t b[4];
                    ldsm4(b, so + ST_B + rB * 64 + bOff);
                    // acc index: mg*4 + (bg*2 + pair)
                    mma16816(acc[bg * 2],     a0, b[0], b[1]);
                    mma16816(acc[bg * 2 + 1], a0, b[2], b[3]);
                    mma16816(acc[4 + bg * 2],     a1, b[0], b[1]);
                    mma16816(acc[4 + bg * 2 + 1], a1, b[2], b[3]);
                }
            }

            if (it + 1 < NITER) STS_TILE((it + 1) & 1);
            __syncthreads();
        }

        // ---- epilogue: write partials ----
        const int g  = lid >> 2;
        const int tg = lid & 3;
        float* part = g_part + (size_t)(t >> 6) * (N_DIM * OUT_CH);
        #pragma unroll
        for (int mg = 0; mg < 2; mg++) {
            const int row0 = mBase + wRow * 32 + mg * 16 + g;
            #pragma unroll
            for (int p = 0; p < 4; p++) {
                const float* c = acc[mg * 4 + p];
                int col = wCol * 32 + p * 8 + tg * 2;
                *reinterpret_cast<float2*>(&part[(size_t)row0 * OUT_CH + col]) =
                    make_float2(c[0], c[1]);
                *reinterpret_cast<float2*>(&part[(size_t)(row0 + 8) * OUT_CH + col]) =
                    make_float2(c[2], c[3]);
            }
        }
        // loop back; the steal-barrier orders epilogue before next STS
    }
}

// ---------------------------------------------------------------------------
// Kernel 3: reduce split-K partials.
//   phase 0: g_bf[n][m] = fp16( filt[m] * sum_s P[s][m][n] )  (fused transpose)
//   phase 1: d_out      = sum_s P[s]
// ---------------------------------------------------------------------------
__global__ __launch_bounds__(256) void reduce_kernel(
    const float* __restrict__ filt, float* __restrict__ outp, int phase)
{
    const int i = blockIdx.x * blockDim.x + threadIdx.x;  // float4 index
    const int stride4 = (N_DIM * OUT_CH) / 4;
    const float4* P = reinterpret_cast<const float4*>(g_part);

    float4 s = P[i];
    #pragma unroll
    for (int sp = 1; sp < SPLITK; sp++) {
        float4 v = P[i + sp * stride4];
        s.x += v.x; s.y += v.y; s.z += v.z; s.w += v.w;
    }
    if (phase == 0) {
        int m = (i * 4) / OUT_CH;     // OUT_CH % 4 == 0 -> constant per float4
        int c = (i * 4) % OUT_CH;
        float f = filt[m];
        g_bf[(size_t)(c + 0) * N_DIM + m] = __float2half(s.x * f);
        g_bf[(size_t)(c + 1) * N_DIM + m] = __float2half(s.y * f);
        g_bf[(size_t)(c + 2) * N_DIM + m] = __float2half(s.z * f);
        g_bf[(size_t)(c + 3) * N_DIM + m] = __float2half(s.w * f);
    } else {
        reinterpret_cast<float4*>(outp)[i] = s;
    }
}

// ---------------------------------------------------------------------------
// Launch. Inputs: features, weight_matrix, filt, wavelets, wavelets_inv.
// No dynamic smem, no attributes, no static state, no device symbols as args.
// ---------------------------------------------------------------------------
extern "C" void kernel_launch(void* const* d_in, const int* in_sizes, int n_in,
                              void* d_out, int out_size)
{
    const float* features     = (const float*)d_in[0];
    const float* weight       = (const float*)d_in[1];
    const float* filt         = (const float*)d_in[2];
    const float* wavelets     = (const float*)d_in[3];
    const float* wavelets_inv = (const float*)d_in[4];
    float* out = (float*)d_out;

    const int redBlocks = (N_DIM * OUT_CH) / 4 / 256;   // 512

    // 1) g_bf = (features @ W)^T as fp16 ; reset tile queues
    lin_kernel<<<N_DIM / 32, 256>>>(features, weight);
    // 2) partials = wavelets_inv @ g_bf^T   (persistent, queue 0)
    mma_gemm<<<PERSIST, GTHREADS>>>(wavelets_inv, 0);
    // 3) g_bf = (filt[:,None] * sum(partials))^T as fp16
    reduce_kernel<<<redBlocks, 256>>>(filt, nullptr, 0);
    // 4) partials = wavelets @ g_bf^T       (persistent, queue 1)
    mma_gemm<<<PERSIST, GTHREADS>>>(wavelets, 1);
    // 5) out = sum(partials)
    reduce_kernel<<<redBlocks, 256>>>(filt, out, 1);
}